// round 2
// baseline (speedup 1.0000x reference)
#include <cuda_runtime.h>
#include <cstddef>

#define B_ 32
#define T_ 2048
#define D_ 256
#define H_ 512
#define O_ 256

// ---------------- scratch (static device globals; no allocation) ----------------
__device__ float g_xw[(size_t)B_ * T_ * H_];   // x @ W_ih^T + biases   [B,T,H]
__device__ float g_z [(size_t)B_ * T_ * H_];   // fallback z buffer
__device__ float g_h [2][B_ * H_];             // double-buffered hidden state
__device__ unsigned g_bar_count;               // grid barrier state (returns to 0)
__device__ unsigned g_bar_sense;               // returns to 0 (even # of barriers)

// ---------------- grid barrier (sense reversing, replay-safe) ----------------
__device__ __forceinline__ void gbar(unsigned* sense)
{
    __syncthreads();
    if (threadIdx.x == 0) {
        unsigned s = (*sense ^= 1u);
        __threadfence();
        unsigned a = atomicAdd(&g_bar_count, 1u);
        if (a == gridDim.x - 1u) {
            atomicExch(&g_bar_count, 0u);
            __threadfence();
            atomicExch(&g_bar_sense, s);
        } else {
            while (*(volatile unsigned*)&g_bar_sense != s) { __nanosleep(64); }
        }
        __threadfence();
    }
    __syncthreads();
}

// ---------------- generic C = A(MxK) * B(NxK)^T + bias ----------------
// 64x64 block tile, BK=16, 256 threads, 4x4 micro-tile.
__global__ __launch_bounds__(256) void gemm_nt_bias(
    const float* __restrict__ A, const float* __restrict__ Bm,
    const float* __restrict__ bias1, const float* __restrict__ bias2,
    float* __restrict__ C, int M, int N, int K)
{
    __shared__ float As[16][68];
    __shared__ float Bs[16][68];
    const int tid = threadIdx.x;
    const int tx = tid & 15, ty = tid >> 4;
    const int m0 = blockIdx.x * 64, n0 = blockIdx.y * 64;

    const int ldRow = tid >> 2;          // 0..63
    const int ldK   = (tid & 3) * 4;     // 0,4,8,12

    float acc[4][4] = {};

    for (int kt = 0; kt < K; kt += 16) {
        float4 av = *(const float4*)&A [(size_t)(m0 + ldRow) * K + kt + ldK];
        float4 bv = *(const float4*)&Bm[(size_t)(n0 + ldRow) * K + kt + ldK];
        As[ldK + 0][ldRow] = av.x; As[ldK + 1][ldRow] = av.y;
        As[ldK + 2][ldRow] = av.z; As[ldK + 3][ldRow] = av.w;
        Bs[ldK + 0][ldRow] = bv.x; Bs[ldK + 1][ldRow] = bv.y;
        Bs[ldK + 2][ldRow] = bv.z; Bs[ldK + 3][ldRow] = bv.w;
        __syncthreads();
        #pragma unroll
        for (int k = 0; k < 16; k++) {
            float4 a4 = *(const float4*)&As[k][ty * 4];
            float4 b4 = *(const float4*)&Bs[k][tx * 4];
            float a[4] = {a4.x, a4.y, a4.z, a4.w};
            float b[4] = {b4.x, b4.y, b4.z, b4.w};
            #pragma unroll
            for (int i = 0; i < 4; i++)
                #pragma unroll
                for (int j = 0; j < 4; j++)
                    acc[i][j] += a[i] * b[j];
        }
        __syncthreads();
    }

    #pragma unroll
    for (int i = 0; i < 4; i++) {
        int m = m0 + ty * 4 + i;
        #pragma unroll
        for (int j = 0; j < 4; j++) {
            int n = n0 + tx * 4 + j;
            float bb = bias1[n] + (bias2 ? bias2[n] : 0.f);
            C[(size_t)m * N + n] = acc[i][j] + bb;
        }
    }
}

// ---------------- sequential scan: h_t = xw_t + h_{t-1} @ W_hh^T ----------------
// 128 CTAs (<= SM count -> co-resident), 128 threads each.
// CTA = (batch group of 4) x (32-column slice). W slice persistent in smem.
// Thread = (2 batches, 1 col, half of K). Partials combined through smem.
#define SCAN_BLOCKS 128
#define SCAN_SMEM ((512 * 32 + 4 * 512 + 128) * 4)

__global__ __launch_bounds__(128) void scan_kernel(
    const float* __restrict__ Whh, const float* __restrict__ h0,
    float* __restrict__ z)
{
    extern __shared__ float sm[];
    float* w_s  = sm;                    // [512][32]  w_s[k*32+c] = W_hh[c0+c][k]
    float* h_s  = sm + 512 * 32;         // [4][512]
    float* part = h_s + 4 * 512;         // [4][32]

    const int tid   = threadIdx.x;
    const int lane  = tid & 31;
    const int wrp   = tid >> 5;
    const int bp    = wrp & 1;           // batch pair within group
    const int khalf = wrp >> 1;          // K half: 0 or 1
    const int bg    = blockIdx.x >> 4;   // 8 batch groups
    const int cg    = blockIdx.x & 15;   // 16 col groups
    const int b0    = bg * 4;
    const int c0    = cg * 32;

    // Load W_hh column slice (transposed) once; persists for all 2048 steps.
    for (int i = tid; i < 512 * 32; i += 128) {
        int k = i >> 5, c = i & 31;
        w_s[i] = Whh[(size_t)(c0 + c) * H_ + k];
    }
    // Initialize h buffer 0 from h0 (each batch group written once, by cg==0).
    if (cg == 0) {
        const float4* src = (const float4*)(h0 + b0 * H_);
        float4* dst = (float4*)(&g_h[0][b0 * H_]);
        for (int i = tid; i < 4 * H_ / 4; i += 128) dst[i] = src[i];
    }

    unsigned sense = 0;
    gbar(&sense);                        // barrier #1

    const int rb0 = b0 + bp * 2;
    const int rb1 = rb0 + 1;

    for (int t = 0; t < T_; t++) {
        const int cur = t & 1;
        // stage h for our 4 batches
        {
            const float4* src = (const float4*)(&g_h[cur][b0 * H_]);
            float4* dst = (float4*)h_s;
            for (int i = tid; i < 512; i += 128) dst[i] = src[i];
        }
        __syncthreads();

        const float4* h4a = (const float4*)(h_s + (bp * 2) * H_)     + khalf * 64;
        const float4* h4b = (const float4*)(h_s + (bp * 2 + 1) * H_) + khalf * 64;
        const float*  wk  = w_s + khalf * 256 * 32 + lane;

        float a0 = 0.f, a1 = 0.f;
        #pragma unroll 4
        for (int q = 0; q < 64; q++) {
            float4 x0 = h4a[q];
            float4 x1 = h4b[q];
            float w0 = wk[(q * 4 + 0) * 32];
            float w1 = wk[(q * 4 + 1) * 32];
            float w2 = wk[(q * 4 + 2) * 32];
            float w3 = wk[(q * 4 + 3) * 32];
            a0 = fmaf(x0.x, w0, a0); a0 = fmaf(x0.y, w1, a0);
            a0 = fmaf(x0.z, w2, a0); a0 = fmaf(x0.w, w3, a0);
            a1 = fmaf(x1.x, w0, a1); a1 = fmaf(x1.y, w1, a1);
            a1 = fmaf(x1.z, w2, a1); a1 = fmaf(x1.w, w3, a1);
        }

        if (khalf == 1) {
            part[(bp * 2 + 0) * 32 + lane] = a0;
            part[(bp * 2 + 1) * 32 + lane] = a1;
        }
        __syncthreads();
        if (khalf == 0) {
            const int c = c0 + lane;
            float r0 = a0 + part[(bp * 2 + 0) * 32 + lane]
                     + g_xw[((size_t)rb0 * T_ + t) * H_ + c];
            float r1 = a1 + part[(bp * 2 + 1) * 32 + lane]
                     + g_xw[((size_t)rb1 * T_ + t) * H_ + c];
            g_h[cur ^ 1][rb0 * H_ + c] = r0;
            g_h[cur ^ 1][rb1 * H_ + c] = r1;
            z[((size_t)rb0 * T_ + t) * H_ + c] = r0;
            z[((size_t)rb1 * T_ + t) * H_ + c] = r1;
        }
        gbar(&sense);                    // barriers #2 .. #2049
    }
    gbar(&sense);                        // barrier #2050 -> even total, sense back to 0
}

// ---------------- softmax over last dim (O=256), in place ----------------
__global__ __launch_bounds__(128) void softmax_kernel(float* __restrict__ p)
{
    const size_t row = blockIdx.x;
    float* r = p + row * O_;
    const int tid = threadIdx.x;

    float v0 = r[tid], v1 = r[tid + 128];
    float m = fmaxf(v0, v1);
    #pragma unroll
    for (int o = 16; o; o >>= 1) m = fmaxf(m, __shfl_xor_sync(~0u, m, o));
    __shared__ float red[4];
    if ((tid & 31) == 0) red[tid >> 5] = m;
    __syncthreads();
    m = fmaxf(fmaxf(red[0], red[1]), fmaxf(red[2], red[3]));

    float e0 = expf(v0 - m), e1 = expf(v1 - m);
    float s = e0 + e1;
    #pragma unroll
    for (int o = 16; o; o >>= 1) s += __shfl_xor_sync(~0u, s, o);
    __shared__ float red2[4];
    if ((tid & 31) == 0) red2[tid >> 5] = s;
    __syncthreads();
    s = red2[0] + red2[1] + red2[2] + red2[3];

    float inv = 1.f / s;
    r[tid] = e0 * inv;
    r[tid + 128] = e1 * inv;
}

// ---------------- launch ----------------
extern "C" void kernel_launch(void* const* d_in, const int* in_sizes, int n_in,
                              void* d_out, int out_size)
{
    const float* x     = (const float*)d_in[0];
    const float* h0    = (const float*)d_in[1];
    const float* W_ih  = (const float*)d_in[2];
    const float* W_hh  = (const float*)d_in[3];
    const float* b_ih  = (const float*)d_in[4];
    const float* b_hh  = (const float*)d_in[5];
    const float* W_lin = (const float*)d_in[6];
    const float* b_lin = (const float*)d_in[7];
    float* out = (float*)d_out;

    const size_t BTO = (size_t)B_ * T_ * O_;
    const size_t BTH = (size_t)B_ * T_ * H_;

    float* z_ptr = nullptr;
    bool do_out = true;
    if ((size_t)out_size >= BTO + BTH) {
        z_ptr = out + BTO;                       // tuple (out, z) flattened
    } else if ((size_t)out_size == BTH) {
        z_ptr = out; do_out = false;             // only z requested
    } else {
        cudaGetSymbolAddress((void**)&z_ptr, g_z);  // only softmax out requested
    }

    float* xw_ptr = nullptr;
    cudaGetSymbolAddress((void**)&xw_ptr, g_xw);

    // K1: xw = x @ W_ih^T + (b_ih + b_hh)
    {
        dim3 g((B_ * T_) / 64, H_ / 64);
        gemm_nt_bias<<<g, 256>>>(x, W_ih, b_ih, b_hh, xw_ptr, B_ * T_, H_, D_);
    }
    // K2: sequential scan producing z
    {
        cudaFuncSetAttribute(scan_kernel,
                             cudaFuncAttributeMaxDynamicSharedMemorySize, SCAN_SMEM);
        scan_kernel<<<SCAN_BLOCKS, 128, SCAN_SMEM>>>(W_hh, h0, z_ptr);
    }
    // K3: logits = z @ W_lin^T + b_lin ; softmax over O
    if (do_out) {
        dim3 g((B_ * T_) / 64, O_ / 64);
        gemm_nt_bias<<<g, 256>>>(z_ptr, W_lin, b_lin, nullptr, out, B_ * T_, O_, H_);
        softmax_kernel<<<B_ * T_, 128>>>(out);
    }
}

// round 3
// speedup vs baseline: 2.3343x; 2.3343x over previous
#include <cuda_runtime.h>
#include <cstddef>

#define B_ 32
#define T_ 2048
#define D_ 256
#define H_ 512
#define O_ 256
#define L_ 32          // chunk length
#define C_ 64          // number of chunks (C_*L_ == T_)
#define M_ (C_*B_)     // 2048 rows in the chunk-parallel step GEMMs

// ---------------- scratch (static device globals; no allocation) ----------------
__device__ float g_xw[(size_t)B_ * T_ * H_];     // x @ W_ih^T + biases   [B,T,H]
__device__ float g_z [(size_t)B_ * T_ * H_];     // fallback z buffer
__device__ float g_S0[(size_t)M_ * H_];          // chunk-state ping
__device__ float g_S1[(size_t)M_ * H_];          // chunk-state pong
__device__ float g_Hst[(size_t)C_ * B_ * H_];    // true chunk-entry states
__device__ float g_P0[(size_t)H_ * H_];          // matrix-power ping
__device__ float g_P1[(size_t)H_ * H_];          // matrix-power pong
__device__ unsigned g_bar_count;
__device__ unsigned g_bar_sense;                 // returns to 0 (even # of barriers)

// ---------------- grid barrier (sense reversing, replay-safe) ----------------
__device__ __forceinline__ void gbar(unsigned* sense)
{
    __syncthreads();
    if (threadIdx.x == 0) {
        unsigned s = (*sense ^= 1u);
        __threadfence();
        unsigned a = atomicAdd(&g_bar_count, 1u);
        if (a == gridDim.x - 1u) {
            atomicExch(&g_bar_count, 0u);
            __threadfence();
            atomicExch(&g_bar_sense, s);
        } else {
            while (*(volatile unsigned*)&g_bar_sense != s) { __nanosleep(64); }
        }
        __threadfence();
    }
    __syncthreads();
}

// =================================================================
// 128x128-tile SGEMM:  C = A(MxK) * Bm(NxK)^T + bias1 (+bias2)
// 256 threads, 8x8 micro-tile (split 4+4), BK=8.
// =================================================================
__global__ __launch_bounds__(256) void gemm128_nt(
    const float* __restrict__ A, const float* __restrict__ Bm,
    const float* __restrict__ bias1, const float* __restrict__ bias2,
    float* __restrict__ C, int M, int N, int K)
{
    __shared__ float As[8][132];
    __shared__ float Bs[8][132];
    const int tid = threadIdx.x;
    const int m0 = blockIdx.x * 128, n0 = blockIdx.y * 128;
    const int tx = tid & 15, ty = tid >> 4;
    const int lr = tid >> 1;            // 0..127
    const int lk = (tid & 1) * 4;       // 0 or 4

    float acc[8][8] = {};

    for (int kt = 0; kt < K; kt += 8) {
        float4 av = *(const float4*)&A [(size_t)(m0 + lr) * K + kt + lk];
        float4 bv = *(const float4*)&Bm[(size_t)(n0 + lr) * K + kt + lk];
        As[lk + 0][lr] = av.x; As[lk + 1][lr] = av.y;
        As[lk + 2][lr] = av.z; As[lk + 3][lr] = av.w;
        Bs[lk + 0][lr] = bv.x; Bs[lk + 1][lr] = bv.y;
        Bs[lk + 2][lr] = bv.z; Bs[lk + 3][lr] = bv.w;
        __syncthreads();
        #pragma unroll
        for (int k = 0; k < 8; k++) {
            float a[8], b[8];
            *(float4*)&a[0] = *(const float4*)&As[k][ty * 4];
            *(float4*)&a[4] = *(const float4*)&As[k][ty * 4 + 64];
            *(float4*)&b[0] = *(const float4*)&Bs[k][tx * 4];
            *(float4*)&b[4] = *(const float4*)&Bs[k][tx * 4 + 64];
            #pragma unroll
            for (int i = 0; i < 8; i++)
                #pragma unroll
                for (int j = 0; j < 8; j++)
                    acc[i][j] += a[i] * b[j];
        }
        __syncthreads();
    }

    #pragma unroll
    for (int i = 0; i < 8; i++) {
        int m = m0 + (i < 4 ? ty * 4 + i : 64 + ty * 4 + i - 4);
        #pragma unroll
        for (int j = 0; j < 8; j++) {
            int n = n0 + (j < 4 ? tx * 4 + j : 64 + tx * 4 + j - 4);
            float bb = bias1[n] + (bias2 ? bias2[n] : 0.f);
            C[(size_t)m * N + n] = acc[i][j] + bb;
        }
    }
}

// =================================================================
// step GEMM (64x64 tile):  Sout = Sin(2048x512) * Whh^T + xw_slice(j)
// Row m = (c*B + b); additive term from xw[b, c*L + j, :]; optional z write.
// =================================================================
__global__ __launch_bounds__(256) void step_kernel(
    const float* __restrict__ Sin, float* __restrict__ Sout,
    const float* __restrict__ Whh, const float* __restrict__ xw,
    float* __restrict__ z, int j)
{
    __shared__ float As[16][68];
    __shared__ float Bs[16][68];
    const int tid = threadIdx.x;
    const int tx = tid & 15, ty = tid >> 4;
    const int m0 = blockIdx.x * 64, n0 = blockIdx.y * 64;
    const int ldRow = tid >> 2;
    const int ldK   = (tid & 3) * 4;

    float acc[4][4] = {};

    for (int kt = 0; kt < H_; kt += 16) {
        float4 av = *(const float4*)&Sin[(size_t)(m0 + ldRow) * H_ + kt + ldK];
        float4 bv = *(const float4*)&Whh[(size_t)(n0 + ldRow) * H_ + kt + ldK];
        As[ldK + 0][ldRow] = av.x; As[ldK + 1][ldRow] = av.y;
        As[ldK + 2][ldRow] = av.z; As[ldK + 3][ldRow] = av.w;
        Bs[ldK + 0][ldRow] = bv.x; Bs[ldK + 1][ldRow] = bv.y;
        Bs[ldK + 2][ldRow] = bv.z; Bs[ldK + 3][ldRow] = bv.w;
        __syncthreads();
        #pragma unroll
        for (int k = 0; k < 16; k++) {
            float4 a4 = *(const float4*)&As[k][ty * 4];
            float4 b4 = *(const float4*)&Bs[k][tx * 4];
            float a[4] = {a4.x, a4.y, a4.z, a4.w};
            float b[4] = {b4.x, b4.y, b4.z, b4.w};
            #pragma unroll
            for (int i = 0; i < 4; i++)
                #pragma unroll
                for (int jj = 0; jj < 4; jj++)
                    acc[i][jj] += a[i] * b[jj];
        }
        __syncthreads();
    }

    #pragma unroll
    for (int i = 0; i < 4; i++) {
        int m = m0 + ty * 4 + i;
        int b = m & (B_ - 1);
        int c = m >> 5;
        size_t rowoff = ((size_t)b * T_ + (size_t)c * L_ + j) * H_;
        #pragma unroll
        for (int jj = 0; jj < 4; jj++) {
            int n = n0 + tx * 4 + jj;
            float v = acc[i][jj] + xw[rowoff + n];
            Sout[(size_t)m * H_ + n] = v;
            if (z) z[rowoff + n] = v;
        }
    }
}

// phase A init: S row m <- xw[b, c*L + 0, :]
__global__ __launch_bounds__(128) void copy_b0(float* __restrict__ Sout,
                                               const float* __restrict__ xw)
{
    const int m = blockIdx.x;
    const int b = m & (B_ - 1);
    const int c = m >> 5;
    const float4* src = (const float4*)(xw + ((size_t)b * T_ + (size_t)c * L_) * H_);
    float4* dst = (float4*)(Sout + (size_t)m * H_);
    dst[threadIdx.x] = src[threadIdx.x];
}

// =================================================================
// NN matrix squaring: Q = P * P   (512x512), 64x64 tile BK=16
// =================================================================
__global__ __launch_bounds__(256) void matsq_nn(const float* __restrict__ P,
                                                float* __restrict__ Q)
{
    __shared__ float As[16][68];
    __shared__ float Bs[16][68];
    const int tid = threadIdx.x;
    const int tx = tid & 15, ty = tid >> 4;
    const int m0 = blockIdx.x * 64, n0 = blockIdx.y * 64;
    const int ldRow = tid >> 2, ldK = (tid & 3) * 4;     // A loader
    const int krow = tid >> 4, ncol = (tid & 15) * 4;    // B loader

    float acc[4][4] = {};

    for (int kt = 0; kt < H_; kt += 16) {
        float4 av = *(const float4*)&P[(size_t)(m0 + ldRow) * H_ + kt + ldK];
        As[ldK + 0][ldRow] = av.x; As[ldK + 1][ldRow] = av.y;
        As[ldK + 2][ldRow] = av.z; As[ldK + 3][ldRow] = av.w;
        float4 bv = *(const float4*)&P[(size_t)(kt + krow) * H_ + n0 + ncol];
        *(float4*)&Bs[krow][ncol] = bv;
        __syncthreads();
        #pragma unroll
        for (int k = 0; k < 16; k++) {
            float4 a4 = *(const float4*)&As[k][ty * 4];
            float4 b4 = *(const float4*)&Bs[k][tx * 4];
            float a[4] = {a4.x, a4.y, a4.z, a4.w};
            float b[4] = {b4.x, b4.y, b4.z, b4.w};
            #pragma unroll
            for (int i = 0; i < 4; i++)
                #pragma unroll
                for (int jj = 0; jj < 4; jj++)
                    acc[i][jj] += a[i] * b[jj];
        }
        __syncthreads();
    }
    #pragma unroll
    for (int i = 0; i < 4; i++)
        #pragma unroll
        for (int jj = 0; jj < 4; jj++)
            Q[(size_t)(m0 + ty * 4 + i) * H_ + n0 + tx * 4 + jj] = acc[i][jj];
}

// =================================================================
// phase B: sequential chunk-boundary recurrence (persistent, 64 CTAs)
//   Hst[0]   = h0
//   Hst[c]   = Hst[c-1] @ WL^T + sA[c-1]        (c = 1..C-1)
// warp <-> output column n, lane <-> batch b.
// =================================================================
#define HS_STRIDE 516
__global__ __launch_bounds__(256) void phaseB_kernel(
    const float* __restrict__ h0, const float* __restrict__ WL,
    const float* __restrict__ sA, float* __restrict__ Hst)
{
    extern __shared__ float h_s[];           // [32][HS_STRIDE]
    const int tid = threadIdx.x;

    // Hst[0] = h0 (16384 floats over 64 CTAs * 256 threads)
    Hst[blockIdx.x * 256 + tid] = h0[blockIdx.x * 256 + tid];

    unsigned sense = 0;
    gbar(&sense);                            // barrier #1

    const int wrp = tid >> 5, lane = tid & 31;
    const int n = blockIdx.x * 8 + wrp;      // 64*8 = 512 columns
    const float4* wrow = (const float4*)(WL + (size_t)n * H_);

    for (int c = 1; c < C_; c++) {
        // stage previous state [32][512] into padded smem
        const float4* src = (const float4*)(Hst + (size_t)(c - 1) * (B_ * H_));
        for (int i = tid; i < (B_ * H_) / 4; i += 256) {
            int b = i >> 7, k4 = i & 127;
            *(float4*)&h_s[b * HS_STRIDE + k4 * 4] = src[i];
        }
        __syncthreads();

        const float4* hb = (const float4*)(h_s + lane * HS_STRIDE);
        float acc = 0.f;
        #pragma unroll 4
        for (int q = 0; q < 128; q++) {
            float4 hv = hb[q];
            float4 wv = wrow[q];
            acc = fmaf(hv.x, wv.x, acc);
            acc = fmaf(hv.y, wv.y, acc);
            acc = fmaf(hv.z, wv.z, acc);
            acc = fmaf(hv.w, wv.w, acc);
        }
        Hst[(size_t)c * (B_ * H_) + lane * H_ + n] =
            acc + sA[((size_t)(c - 1) * B_ + lane) * H_ + n];
        gbar(&sense);                        // barriers #2..#64  (total 64, even)
    }
}

// ---------------- softmax over last dim (O=256), in place ----------------
__global__ __launch_bounds__(128) void softmax_kernel(float* __restrict__ p)
{
    const size_t row = blockIdx.x;
    float* r = p + row * O_;
    const int tid = threadIdx.x;

    float v0 = r[tid], v1 = r[tid + 128];
    float m = fmaxf(v0, v1);
    #pragma unroll
    for (int o = 16; o; o >>= 1) m = fmaxf(m, __shfl_xor_sync(~0u, m, o));
    __shared__ float red[4];
    if ((tid & 31) == 0) red[tid >> 5] = m;
    __syncthreads();
    m = fmaxf(fmaxf(red[0], red[1]), fmaxf(red[2], red[3]));

    float e0 = expf(v0 - m), e1 = expf(v1 - m);
    float s = e0 + e1;
    #pragma unroll
    for (int o = 16; o; o >>= 1) s += __shfl_xor_sync(~0u, s, o);
    __shared__ float red2[4];
    if ((tid & 31) == 0) red2[tid >> 5] = s;
    __syncthreads();
    s = red2[0] + red2[1] + red2[2] + red2[3];

    float inv = 1.f / s;
    r[tid] = e0 * inv;
    r[tid + 128] = e1 * inv;
}

// ---------------- launch ----------------
extern "C" void kernel_launch(void* const* d_in, const int* in_sizes, int n_in,
                              void* d_out, int out_size)
{
    const float* x     = (const float*)d_in[0];
    const float* h0    = (const float*)d_in[1];
    const float* W_ih  = (const float*)d_in[2];
    const float* W_hh  = (const float*)d_in[3];
    const float* b_ih  = (const float*)d_in[4];
    const float* b_hh  = (const float*)d_in[5];
    const float* W_lin = (const float*)d_in[6];
    const float* b_lin = (const float*)d_in[7];
    float* out = (float*)d_out;

    const size_t BTO = (size_t)B_ * T_ * O_;
    const size_t BTH = (size_t)B_ * T_ * H_;

    float* z_ptr = nullptr;
    bool do_out = true;
    if ((size_t)out_size >= BTO + BTH) {
        z_ptr = out + BTO;                          // tuple (out, z) flattened
    } else if ((size_t)out_size == BTH) {
        z_ptr = out; do_out = false;                // only z requested
    } else {
        cudaGetSymbolAddress((void**)&z_ptr, g_z);  // only softmax out requested
    }

    float *xw_p, *S0, *S1, *Hst, *P0, *P1;
    cudaGetSymbolAddress((void**)&xw_p, g_xw);
    cudaGetSymbolAddress((void**)&S0,  g_S0);
    cudaGetSymbolAddress((void**)&S1,  g_S1);
    cudaGetSymbolAddress((void**)&Hst, g_Hst);
    cudaGetSymbolAddress((void**)&P0,  g_P0);
    cudaGetSymbolAddress((void**)&P1,  g_P1);

    // K1: xw = x @ W_ih^T + (b_ih + b_hh)        [65536 x 512], K=256
    {
        dim3 g((B_ * T_) / 128, H_ / 128);
        gemm128_nt<<<g, 256>>>(x, W_ih, b_ih, b_hh, xw_p, B_ * T_, H_, D_);
    }

    // WL = Whh^32 via 5 squarings (2,4,8,16,32) -> ends in P0
    {
        dim3 g(H_ / 64, H_ / 64);
        matsq_nn<<<g, 256>>>(W_hh, P0);
        matsq_nn<<<g, 256>>>(P0, P1);
        matsq_nn<<<g, 256>>>(P1, P0);
        matsq_nn<<<g, 256>>>(P0, P1);
        matsq_nn<<<g, 256>>>(P1, P0);
    }

    // Phase A: zero-init chunk scan -> s_c (no z writes)
    {
        dim3 g(M_ / 64, H_ / 64);
        copy_b0<<<M_, 128>>>(S0, xw_p);                        // jj = 0
        for (int jj = 1; jj < L_; jj++) {
            float* in  = (jj & 1) ? S0 : S1;
            float* outb= (jj & 1) ? S1 : S0;
            step_kernel<<<g, 256>>>(in, outb, W_hh, xw_p, nullptr, jj);
        }
        // s_c lives in S1 (jj=31 odd)
    }

    // Phase B: boundary states
    {
        cudaFuncSetAttribute(phaseB_kernel,
                             cudaFuncAttributeMaxDynamicSharedMemorySize,
                             B_ * HS_STRIDE * 4);
        phaseB_kernel<<<C_, 256, B_ * HS_STRIDE * 4>>>(h0, P0, S1, Hst);
    }

    // Phase C: correct-init chunk scan, writing z
    {
        dim3 g(M_ / 64, H_ / 64);
        step_kernel<<<g, 256>>>(Hst, S0, W_hh, xw_p, z_ptr, 0); // jj = 0
        for (int jj = 1; jj < L_; jj++) {
            float* in  = (jj & 1) ? S0 : S1;
            float* outb= (jj & 1) ? S1 : S0;
            step_kernel<<<g, 256>>>(in, outb, W_hh, xw_p, z_ptr, jj);
        }
    }

    // K3: logits = z @ W_lin^T + b_lin ; softmax over O
    if (do_out) {
        dim3 g((B_ * T_) / 128, O_ / 128);
        gemm128_nt<<<g, 256>>>(z_ptr, W_lin, b_lin, nullptr, out, B_ * T_, O_, H_);
        softmax_kernel<<<B_ * T_, 128>>>(out);
    }
}

// round 9
// speedup vs baseline: 2.3578x; 1.0100x over previous
#include <cuda_runtime.h>
#include <cstddef>

#define B_ 32
#define T_ 2048
#define D_ 256
#define H_ 512
#define O_ 256
#define L_ 32          // chunk length
#define C_ 64          // number of chunks (C_*L_ == T_)
#define M_ (C_*B_)     // 2048 rows in the chunk-parallel step GEMMs

// ---------------- scratch (static device globals; no allocation) ----------------
__device__ float g_xw[(size_t)B_ * T_ * H_];     // x @ W_ih^T + biases   [B,T,H]
__device__ float g_z [(size_t)B_ * T_ * H_];     // fallback z buffer
__device__ float g_S0[(size_t)M_ * H_];          // chunk-state ping
__device__ float g_S1[(size_t)M_ * H_];          // chunk-state pong
__device__ float g_Hst[(size_t)C_ * B_ * H_];    // true chunk-entry states
__device__ float g_P0[(size_t)H_ * H_];          // matrix-power ping
__device__ float g_P1[(size_t)H_ * H_];          // matrix-power pong
__device__ unsigned g_bar_count;
__device__ unsigned g_bar_sense;                 // returns to 0 (even # of barriers)

// ---------------- grid barrier (sense reversing, replay-safe) ----------------
__device__ __forceinline__ void gbar(unsigned* sense)
{
    __syncthreads();
    if (threadIdx.x == 0) {
        unsigned s = (*sense ^= 1u);
        __threadfence();
        unsigned a = atomicAdd(&g_bar_count, 1u);
        if (a == gridDim.x - 1u) {
            atomicExch(&g_bar_count, 0u);
            __threadfence();
            atomicExch(&g_bar_sense, s);
        } else {
            while (*(volatile unsigned*)&g_bar_sense != s) { __nanosleep(64); }
        }
        __threadfence();
    }
    __syncthreads();
}

// =================================================================
// 128x128-tile SGEMM:  C = A(MxK) * Bm(NxK)^T + bias1 (+bias2)
// 256 threads, 8x8 micro-tile (split 4+4), BK=8.   (proven in R3)
// =================================================================
__global__ __launch_bounds__(256) void gemm128_nt(
    const float* __restrict__ A, const float* __restrict__ Bm,
    const float* __restrict__ bias1, const float* __restrict__ bias2,
    float* __restrict__ C, int M, int N, int K)
{
    __shared__ float As[8][132];
    __shared__ float Bs[8][132];
    const int tid = threadIdx.x;
    const int m0 = blockIdx.x * 128, n0 = blockIdx.y * 128;
    const int tx = tid & 15, ty = tid >> 4;
    const int lr = tid >> 1;            // 0..127
    const int lk = (tid & 1) * 4;       // 0 or 4

    float acc[8][8] = {};

    for (int kt = 0; kt < K; kt += 8) {
        float4 av = *(const float4*)&A [(size_t)(m0 + lr) * K + kt + lk];
        float4 bv = *(const float4*)&Bm[(size_t)(n0 + lr) * K + kt + lk];
        As[lk + 0][lr] = av.x; As[lk + 1][lr] = av.y;
        As[lk + 2][lr] = av.z; As[lk + 3][lr] = av.w;
        Bs[lk + 0][lr] = bv.x; Bs[lk + 1][lr] = bv.y;
        Bs[lk + 2][lr] = bv.z; Bs[lk + 3][lr] = bv.w;
        __syncthreads();
        #pragma unroll
        for (int k = 0; k < 8; k++) {
            float a[8], b[8];
            *(float4*)&a[0] = *(const float4*)&As[k][ty * 4];
            *(float4*)&a[4] = *(const float4*)&As[k][ty * 4 + 64];
            *(float4*)&b[0] = *(const float4*)&Bs[k][tx * 4];
            *(float4*)&b[4] = *(const float4*)&Bs[k][tx * 4 + 64];
            #pragma unroll
            for (int i = 0; i < 8; i++)
                #pragma unroll
                for (int j = 0; j < 8; j++)
                    acc[i][j] += a[i] * b[j];
        }
        __syncthreads();
    }

    #pragma unroll
    for (int i = 0; i < 8; i++) {
        int m = m0 + (i < 4 ? ty * 4 + i : 64 + ty * 4 + i - 4);
        #pragma unroll
        for (int j = 0; j < 8; j++) {
            int n = n0 + (j < 4 ? tx * 4 + j : 64 + tx * 4 + j - 4);
            float bb = bias1[n] + (bias2 ? bias2[n] : 0.f);
            C[(size_t)m * N + n] = acc[i][j] + bb;
        }
    }
}

// =================================================================
// step GEMM v2 (128x64 tile, 8x4 micro, BK=16):
//   Sout = Sin(2048x512) * Whh^T + xw_slice(j)
// Row m = (c*B + b); additive term from xw[b, c*L + j, :]; optional z write.
// grid (16, 8) = 128 CTAs -> one wave on 148 SMs.
// =================================================================
__global__ __launch_bounds__(256) void step_kernel(
    const float* __restrict__ Sin, float* __restrict__ Sout,
    const float* __restrict__ Whh, const float* __restrict__ xw,
    float* __restrict__ z, int j)
{
    __shared__ float As[16][132];
    __shared__ float Bs[16][68];
    const int tid = threadIdx.x;
    const int tx = tid & 15, ty = tid >> 4;          // micro: 8 rows x 4 cols
    const int m0 = blockIdx.x * 128, n0 = blockIdx.y * 64;
    const int aRow = tid >> 1, aK = (tid & 1) * 8;   // A loader: 2x float4
    const int bRow = tid >> 2, bK = (tid & 3) * 4;   // B loader: 1x float4

    float acc[8][4] = {};

    for (int kt = 0; kt < H_; kt += 16) {
        float4 a0 = *(const float4*)&Sin[(size_t)(m0 + aRow) * H_ + kt + aK];
        float4 a1 = *(const float4*)&Sin[(size_t)(m0 + aRow) * H_ + kt + aK + 4];
        float4 bv = *(const float4*)&Whh[(size_t)(n0 + bRow) * H_ + kt + bK];
        As[aK + 0][aRow] = a0.x; As[aK + 1][aRow] = a0.y;
        As[aK + 2][aRow] = a0.z; As[aK + 3][aRow] = a0.w;
        As[aK + 4][aRow] = a1.x; As[aK + 5][aRow] = a1.y;
        As[aK + 6][aRow] = a1.z; As[aK + 7][aRow] = a1.w;
        Bs[bK + 0][bRow] = bv.x; Bs[bK + 1][bRow] = bv.y;
        Bs[bK + 2][bRow] = bv.z; Bs[bK + 3][bRow] = bv.w;
        __syncthreads();
        #pragma unroll
        for (int k = 0; k < 16; k++) {
            float a[8], b[4];
            *(float4*)&a[0] = *(const float4*)&As[k][ty * 8];
            *(float4*)&a[4] = *(const float4*)&As[k][ty * 8 + 4];
            *(float4*)&b[0] = *(const float4*)&Bs[k][tx * 4];
            #pragma unroll
            for (int i = 0; i < 8; i++)
                #pragma unroll
                for (int jj = 0; jj < 4; jj++)
                    acc[i][jj] += a[i] * b[jj];
        }
        __syncthreads();
    }

    #pragma unroll
    for (int i = 0; i < 8; i++) {
        int m = m0 + ty * 8 + i;
        int b = m & (B_ - 1);
        int c = m >> 5;
        size_t rowoff = ((size_t)b * T_ + (size_t)c * L_ + j) * H_;
        #pragma unroll
        for (int jj = 0; jj < 4; jj++) {
            int n = n0 + tx * 4 + jj;
            float v = acc[i][jj] + xw[rowoff + n];
            Sout[(size_t)m * H_ + n] = v;
            if (z) z[rowoff + n] = v;
        }
    }
}

// phase A init: S row m <- xw[b, c*L + 0, :]
__global__ __launch_bounds__(128) void copy_b0(float* __restrict__ Sout,
                                               const float* __restrict__ xw)
{
    const int m = blockIdx.x;
    const int b = m & (B_ - 1);
    const int c = m >> 5;
    const float4* src = (const float4*)(xw + ((size_t)b * T_ + (size_t)c * L_) * H_);
    float4* dst = (float4*)(Sout + (size_t)m * H_);
    dst[threadIdx.x] = src[threadIdx.x];
}

// =================================================================
// NN matrix squaring: Q = P * P   (512x512), 64x64 tile BK=16
// =================================================================
__global__ __launch_bounds__(256) void matsq_nn(const float* __restrict__ P,
                                                float* __restrict__ Q)
{
    __shared__ float As[16][68];
    __shared__ float Bs[16][68];
    const int tid = threadIdx.x;
    const int tx = tid & 15, ty = tid >> 4;
    const int m0 = blockIdx.x * 64, n0 = blockIdx.y * 64;
    const int ldRow = tid >> 2, ldK = (tid & 3) * 4;     // A loader
    const int krow = tid >> 4, ncol = (tid & 15) * 4;    // B loader

    float acc[4][4] = {};

    for (int kt = 0; kt < H_; kt += 16) {
        float4 av = *(const float4*)&P[(size_t)(m0 + ldRow) * H_ + kt + ldK];
        As[ldK + 0][ldRow] = av.x; As[ldK + 1][ldRow] = av.y;
        As[ldK + 2][ldRow] = av.z; As[ldK + 3][ldRow] = av.w;
        float4 bv = *(const float4*)&P[(size_t)(kt + krow) * H_ + n0 + ncol];
        *(float4*)&Bs[krow][ncol] = bv;
        __syncthreads();
        #pragma unroll
        for (int k = 0; k < 16; k++) {
            float4 a4 = *(const float4*)&As[k][ty * 4];
            float4 b4 = *(const float4*)&Bs[k][tx * 4];
            float a[4] = {a4.x, a4.y, a4.z, a4.w};
            float b[4] = {b4.x, b4.y, b4.z, b4.w};
            #pragma unroll
            for (int i = 0; i < 4; i++)
                #pragma unroll
                for (int jj = 0; jj < 4; jj++)
                    acc[i][jj] += a[i] * b[jj];
        }
        __syncthreads();
    }
    #pragma unroll
    for (int i = 0; i < 4; i++)
        #pragma unroll
        for (int jj = 0; jj < 4; jj++)
            Q[(size_t)(m0 + ty * 4 + i) * H_ + n0 + tx * 4 + jj] = acc[i][jj];
}

// =================================================================
// phase B: sequential chunk-boundary recurrence (persistent, 64 CTAs)
//   Hst[0] = h0 ;  Hst[c] = Hst[c-1] @ WL^T + sA[c-1]
// =================================================================
#define HS_STRIDE 516
__global__ __launch_bounds__(256) void phaseB_kernel(
    const float* __restrict__ h0, const float* __restrict__ WL,
    const float* __restrict__ sA, float* __restrict__ Hst)
{
    extern __shared__ float h_s[];           // [32][HS_STRIDE]
    const int tid = threadIdx.x;

    Hst[blockIdx.x * 256 + tid] = h0[blockIdx.x * 256 + tid];

    unsigned sense = 0;
    gbar(&sense);                            // barrier #1

    const int wrp = tid >> 5, lane = tid & 31;
    const int n = blockIdx.x * 8 + wrp;      // 64*8 = 512 columns
    const float4* wrow = (const float4*)(WL + (size_t)n * H_);

    for (int c = 1; c < C_; c++) {
        const float4* src = (const float4*)(Hst + (size_t)(c - 1) * (B_ * H_));
        for (int i = tid; i < (B_ * H_) / 4; i += 256) {
            int b = i >> 7, k4 = i & 127;
            *(float4*)&h_s[b * HS_STRIDE + k4 * 4] = src[i];
        }
        __syncthreads();

        const float4* hb = (const float4*)(h_s + lane * HS_STRIDE);
        float acc = 0.f;
        #pragma unroll 4
        for (int q = 0; q < 128; q++) {
            float4 hv = hb[q];
            float4 wv = wrow[q];
            acc = fmaf(hv.x, wv.x, acc); acc = fmaf(hv.y, wv.y, acc);
            acc = fmaf(hv.z, wv.z, acc); acc = fmaf(hv.w, wv.w, acc);
        }
        Hst[(size_t)c * (B_ * H_) + lane * H_ + n] =
            acc + sA[((size_t)(c - 1) * B_ + lane) * H_ + n];
        gbar(&sense);                        // barriers #2..#64 (total 64, even)
    }
}

// ---------------- softmax over last dim (O=256), in place ----------------
__global__ __launch_bounds__(128) void softmax_kernel(float* __restrict__ p)
{
    const size_t row = blockIdx.x;
    float* r = p + row * O_;
    const int tid = threadIdx.x;

    float v0 = r[tid], v1 = r[tid + 128];
    float m = fmaxf(v0, v1);
    #pragma unroll
    for (int o = 16; o; o >>= 1) m = fmaxf(m, __shfl_xor_sync(~0u, m, o));
    __shared__ float red[4];
    if ((tid & 31) == 0) red[tid >> 5] = m;
    __syncthreads();
    m = fmaxf(fmaxf(red[0], red[1]), fmaxf(red[2], red[3]));

    float e0 = expf(v0 - m), e1 = expf(v1 - m);
    float s = e0 + e1;
    #pragma unroll
    for (int o = 16; o; o >>= 1) s += __shfl_xor_sync(~0u, s, o);
    __shared__ float red2[4];
    if ((tid & 31) == 0) red2[tid >> 5] = s;
    __syncthreads();
    s = red2[0] + red2[1] + red2[2] + red2[3];

    float inv = 1.f / s;
    r[tid] = e0 * inv;
    r[tid + 128] = e1 * inv;
}

// ---------------- launch ----------------
extern "C" void kernel_launch(void* const* d_in, const int* in_sizes, int n_in,
                              void* d_out, int out_size)
{
    const float* x     = (const float*)d_in[0];
    const float* h0    = (const float*)d_in[1];
    const float* W_ih  = (const float*)d_in[2];
    const float* W_hh  = (const float*)d_in[3];
    const float* b_ih  = (const float*)d_in[4];
    const float* b_hh  = (const float*)d_in[5];
    const float* W_lin = (const float*)d_in[6];
    const float* b_lin = (const float*)d_in[7];
    float* out = (float*)d_out;

    const size_t BTO = (size_t)B_ * T_ * O_;
    const size_t BTH = (size_t)B_ * T_ * H_;

    float* z_ptr = nullptr;
    bool do_out = true;
    if ((size_t)out_size >= BTO + BTH) {
        z_ptr = out + BTO;                          // tuple (out, z) flattened
    } else if ((size_t)out_size == BTH) {
        z_ptr = out; do_out = false;                // only z requested
    } else {
        cudaGetSymbolAddress((void**)&z_ptr, g_z);  // only softmax out requested
    }

    float *xw_p, *S0, *S1, *Hst, *P0, *P1;
    cudaGetSymbolAddress((void**)&xw_p, g_xw);
    cudaGetSymbolAddress((void**)&S0,  g_S0);
    cudaGetSymbolAddress((void**)&S1,  g_S1);
    cudaGetSymbolAddress((void**)&Hst, g_Hst);
    cudaGetSymbolAddress((void**)&P0,  g_P0);
    cudaGetSymbolAddress((void**)&P1,  g_P1);

    // K1: xw = x @ W_ih^T + (b_ih + b_hh)        [65536 x 512], K=256
    {
        dim3 g((B_ * T_) / 128, H_ / 128);
        gemm128_nt<<<g, 256>>>(x, W_ih, b_ih, b_hh, xw_p, B_ * T_, H_, D_);
    }

    // WL = Whh^32 via 5 squarings (2,4,8,16,32) -> ends in P0
    {
        dim3 g(H_ / 64, H_ / 64);
        matsq_nn<<<g, 256>>>(W_hh, P0);
        matsq_nn<<<g, 256>>>(P0, P1);
        matsq_nn<<<g, 256>>>(P1, P0);
        matsq_nn<<<g, 256>>>(P0, P1);
        matsq_nn<<<g, 256>>>(P1, P0);
    }

    // Phase A: zero-init chunk scan -> s_c (no z writes)
    {
        dim3 g(M_ / 128, H_ / 64);
        copy_b0<<<M_, 128>>>(S0, xw_p);                        // jj = 0
        for (int jj = 1; jj < L_; jj++) {
            float* in  = (jj & 1) ? S0 : S1;
            float* outb= (jj & 1) ? S1 : S0;
            step_kernel<<<g, 256>>>(in, outb, W_hh, xw_p, nullptr, jj);
        }
        // s_c lives in S1 (jj=31 odd)
    }

    // Phase B: boundary states
    {
        cudaFuncSetAttribute(phaseB_kernel,
                             cudaFuncAttributeMaxDynamicSharedMemorySize,
                             B_ * HS_STRIDE * 4);
        phaseB_kernel<<<C_, 256, B_ * HS_STRIDE * 4>>>(h0, P0, S1, Hst);
    }

    // Phase C: correct-init chunk scan, writing z
    {
        dim3 g(M_ / 128, H_ / 64);
        step_kernel<<<g, 256>>>(Hst, S0, W_hh, xw_p, z_ptr, 0); // jj = 0
        for (int jj = 1; jj < L_; jj++) {
            float* in  = (jj & 1) ? S0 : S1;
            float* outb= (jj & 1) ? S1 : S0;
            step_kernel<<<g, 256>>>(in, outb, W_hh, xw_p, z_ptr, jj);
        }
    }

    // K3: logits = z @ W_lin^T + b_lin ; softmax over O
    if (do_out) {
        dim3 g((B_ * T_) / 128, O_ / 128);
        gemm128_nt<<<g, 256>>>(z_ptr, W_lin, b_lin, nullptr, out, B_ * T_, O_, H_);
        softmax_kernel<<<B_ * T_, 128>>>(out);
    }
}

// round 10
// speedup vs baseline: 2.8087x; 1.1913x over previous
#include <cuda_runtime.h>
#include <cstddef>

#define B_ 32
#define T_ 2048
#define D_ 256
#define H_ 512
#define O_ 256
#define L_ 32          // chunk length
#define C_ 64          // number of chunks
#define M_ (C_*B_)     // 2048 rows in chunk-parallel step GEMMs

// ---------------- scratch (static device globals; no allocation) ----------------
__device__ float g_xw[(size_t)B_ * T_ * H_];
__device__ float g_z [(size_t)B_ * T_ * H_];
__device__ float g_SA[(size_t)M_ * H_];
__device__ float g_SB[(size_t)M_ * H_];
__device__ float g_Hst[(size_t)C_ * B_ * H_];
__device__ float g_P0[(size_t)H_ * H_];
__device__ float g_P1[(size_t)H_ * H_];
__device__ unsigned g_bar_count;
__device__ unsigned g_bar_sense;

// ---------------- grid barrier (sense reversing, replay-safe, proven) ----------------
__device__ __forceinline__ void gbar(unsigned* sense)
{
    __syncthreads();
    if (threadIdx.x == 0) {
        unsigned s = (*sense ^= 1u);
        __threadfence();
        unsigned a = atomicAdd(&g_bar_count, 1u);
        if (a == gridDim.x - 1u) {
            atomicExch(&g_bar_count, 0u);
            __threadfence();
            atomicExch(&g_bar_sense, s);
        } else {
            while (*(volatile unsigned*)&g_bar_sense != s) { __nanosleep(64); }
        }
        __threadfence();
    }
    __syncthreads();
}

// =================================================================
// 128x128-tile SGEMM + register prefetch: C = A(MxK)*Bm(NxK)^T + bias
// =================================================================
__global__ __launch_bounds__(256) void gemm128_nt(
    const float* __restrict__ A, const float* __restrict__ Bm,
    const float* __restrict__ bias1, const float* __restrict__ bias2,
    float* __restrict__ C, int M, int N, int K)
{
    __shared__ float As[8][132];
    __shared__ float Bs[8][132];
    const int tid = threadIdx.x;
    const int m0 = blockIdx.x * 128, n0 = blockIdx.y * 128;
    const int tx = tid & 15, ty = tid >> 4;
    const int lr = tid >> 1;
    const int lk = (tid & 1) * 4;

    float acc[8][8] = {};

    float4 av = *(const float4*)&A [(size_t)(m0 + lr) * K + lk];
    float4 bv = *(const float4*)&Bm[(size_t)(n0 + lr) * K + lk];

    for (int kt = 0; kt < K; kt += 8) {
        As[lk + 0][lr] = av.x; As[lk + 1][lr] = av.y;
        As[lk + 2][lr] = av.z; As[lk + 3][lr] = av.w;
        Bs[lk + 0][lr] = bv.x; Bs[lk + 1][lr] = bv.y;
        Bs[lk + 2][lr] = bv.z; Bs[lk + 3][lr] = bv.w;
        __syncthreads();
        if (kt + 8 < K) {
            av = *(const float4*)&A [(size_t)(m0 + lr) * K + kt + 8 + lk];
            bv = *(const float4*)&Bm[(size_t)(n0 + lr) * K + kt + 8 + lk];
        }
        #pragma unroll
        for (int k = 0; k < 8; k++) {
            float a[8], b[8];
            *(float4*)&a[0] = *(const float4*)&As[k][ty * 4];
            *(float4*)&a[4] = *(const float4*)&As[k][ty * 4 + 64];
            *(float4*)&b[0] = *(const float4*)&Bs[k][tx * 4];
            *(float4*)&b[4] = *(const float4*)&Bs[k][tx * 4 + 64];
            #pragma unroll
            for (int i = 0; i < 8; i++)
                #pragma unroll
                for (int j = 0; j < 8; j++)
                    acc[i][j] += a[i] * b[j];
        }
        __syncthreads();
    }

    #pragma unroll
    for (int i = 0; i < 8; i++) {
        int m = m0 + (i < 4 ? ty * 4 + i : 64 + ty * 4 + i - 4);
        #pragma unroll
        for (int j = 0; j < 8; j++) {
            int n = n0 + (j < 4 ? tx * 4 + j : 64 + tx * 4 + j - 4);
            float bb = bias1[n] + (bias2 ? bias2[n] : 0.f);
            C[(size_t)m * N + n] = acc[i][j] + bb;
        }
    }
}

// =================================================================
// persistent chunk-scan kernel (128 CTAs, co-resident):
//   repeat nsteps: S_new = S_old @ Whh^T + xw_slice(jj) [, z write]
// CTA tile 128x64; W slice (64x512) resident in smem for all steps.
//   init == nullptr -> first step reads xw slice (j0-1) as initial state.
//   z != nullptr    -> write z each step; skip Sout write on last step.
// =================================================================
#define SCAN_SMEM ((512 * 68 + 16 * 132) * 4)

__global__ __launch_bounds__(256) void scan_persist(
    const float* __restrict__ init, float* __restrict__ Sping,
    float* __restrict__ Spong, const float* __restrict__ Whh,
    const float* __restrict__ xw, float* __restrict__ z,
    int j0, int nsteps, int pad)
{
    extern __shared__ float sm[];
    float* Ws = sm;               // [512][68]  Ws[k*68 + n_local]
    float* As = sm + 512 * 68;    // [16][132]  As[k*132 + m_local]

    const int tid = threadIdx.x;
    const int tx = tid & 15, ty = tid >> 4;
    const int m0 = (blockIdx.x & 15) * 128;
    const int n0 = (blockIdx.x >> 4) * 64;
    const int aRow = tid >> 1, aK = (tid & 1) * 8;

    // Load W slice once (persists across all steps).
    for (int idx = tid; idx < 64 * 128; idx += 256) {
        int r = idx >> 7, k4 = (idx & 127) * 4;
        float4 w = *(const float4*)&Whh[(size_t)(n0 + r) * H_ + k4];
        Ws[(k4 + 0) * 68 + r] = w.x; Ws[(k4 + 1) * 68 + r] = w.y;
        Ws[(k4 + 2) * 68 + r] = w.z; Ws[(k4 + 3) * 68 + r] = w.w;
    }

    const int am = m0 + aRow;
    const size_t aMapBase = ((size_t)(am & 31) * T_ + (size_t)(am >> 5) * L_) * H_;

    unsigned sense = 0;
    for (int s = 0; s < nsteps; s++) {
        const int jj = j0 + s;
        const float* Ap; size_t abase;
        if (s == 0) {
            if (init) { Ap = init; abase = (size_t)am * H_; }
            else      { Ap = xw;   abase = aMapBase + (size_t)(j0 - 1) * H_; }
        } else {
            Ap = (s & 1) ? Sping : Spong;
            abase = (size_t)am * H_;
        }
        float* So = (s & 1) ? Spong : Sping;
        const bool writeS = !(z && s == nsteps - 1);

        float acc[8][4] = {};
        float4 a0 = *(const float4*)&Ap[abase + aK];
        float4 a1 = *(const float4*)&Ap[abase + aK + 4];

        for (int kt = 0; kt < H_; kt += 16) {
            As[(aK + 0) * 132 + aRow] = a0.x; As[(aK + 1) * 132 + aRow] = a0.y;
            As[(aK + 2) * 132 + aRow] = a0.z; As[(aK + 3) * 132 + aRow] = a0.w;
            As[(aK + 4) * 132 + aRow] = a1.x; As[(aK + 5) * 132 + aRow] = a1.y;
            As[(aK + 6) * 132 + aRow] = a1.z; As[(aK + 7) * 132 + aRow] = a1.w;
            __syncthreads();
            if (kt + 16 < H_) {
                a0 = *(const float4*)&Ap[abase + kt + 16 + aK];
                a1 = *(const float4*)&Ap[abase + kt + 16 + aK + 4];
            }
            #pragma unroll
            for (int k = 0; k < 16; k++) {
                float a[8], b[4];
                *(float4*)&a[0] = *(const float4*)&As[k * 132 + ty * 8];
                *(float4*)&a[4] = *(const float4*)&As[k * 132 + ty * 8 + 4];
                *(float4*)&b[0] = *(const float4*)&Ws[(kt + k) * 68 + tx * 4];
                #pragma unroll
                for (int i = 0; i < 8; i++)
                    #pragma unroll
                    for (int jx = 0; jx < 4; jx++)
                        acc[i][jx] += a[i] * b[jx];
            }
            __syncthreads();
        }

        #pragma unroll
        for (int i = 0; i < 8; i++) {
            int m = m0 + ty * 8 + i;
            int b = m & (B_ - 1);
            int c = m >> 5;
            size_t rowoff = ((size_t)b * T_ + (size_t)c * L_ + jj) * H_;
            #pragma unroll
            for (int jx = 0; jx < 4; jx++) {
                int n = n0 + tx * 4 + jx;
                float v = acc[i][jx] + xw[rowoff + n];
                if (writeS) So[(size_t)m * H_ + n] = v;
                if (z) z[rowoff + n] = v;
            }
        }
        gbar(&sense);
    }
    if (pad) gbar(&sense);      // keep total barrier count even
}

// =================================================================
// NN matrix squaring: Q = P * P (512x512), 64x64 tile BK=16, prefetch
// =================================================================
__global__ __launch_bounds__(256) void matsq_nn(const float* __restrict__ P,
                                                float* __restrict__ Q)
{
    __shared__ float As[16][68];
    __shared__ float Bs[16][68];
    const int tid = threadIdx.x;
    const int tx = tid & 15, ty = tid >> 4;
    const int m0 = blockIdx.x * 64, n0 = blockIdx.y * 64;
    const int ldRow = tid >> 2, ldK = (tid & 3) * 4;
    const int krow = tid >> 4, ncol = (tid & 15) * 4;

    float acc[4][4] = {};

    float4 av = *(const float4*)&P[(size_t)(m0 + ldRow) * H_ + ldK];
    float4 bv = *(const float4*)&P[(size_t)krow * H_ + n0 + ncol];

    for (int kt = 0; kt < H_; kt += 16) {
        As[ldK + 0][ldRow] = av.x; As[ldK + 1][ldRow] = av.y;
        As[ldK + 2][ldRow] = av.z; As[ldK + 3][ldRow] = av.w;
        *(float4*)&Bs[krow][ncol] = bv;
        __syncthreads();
        if (kt + 16 < H_) {
            av = *(const float4*)&P[(size_t)(m0 + ldRow) * H_ + kt + 16 + ldK];
            bv = *(const float4*)&P[(size_t)(kt + 16 + krow) * H_ + n0 + ncol];
        }
        #pragma unroll
        for (int k = 0; k < 16; k++) {
            float4 a4 = *(const float4*)&As[k][ty * 4];
            float4 b4 = *(const float4*)&Bs[k][tx * 4];
            float a[4] = {a4.x, a4.y, a4.z, a4.w};
            float b[4] = {b4.x, b4.y, b4.z, b4.w};
            #pragma unroll
            for (int i = 0; i < 4; i++)
                #pragma unroll
                for (int jj = 0; jj < 4; jj++)
                    acc[i][jj] += a[i] * b[jj];
        }
        __syncthreads();
    }
    #pragma unroll
    for (int i = 0; i < 4; i++)
        #pragma unroll
        for (int jj = 0; jj < 4; jj++)
            Q[(size_t)(m0 + ty * 4 + i) * H_ + n0 + tx * 4 + jj] = acc[i][jj];
}

// =================================================================
// phase B: sequential chunk-boundary recurrence (64 CTAs, proven)
// =================================================================
#define HS_STRIDE 516
__global__ __launch_bounds__(256) void phaseB_kernel(
    const float* __restrict__ h0, const float* __restrict__ WL,
    const float* __restrict__ sA, float* __restrict__ Hst)
{
    extern __shared__ float h_s[];
    const int tid = threadIdx.x;

    Hst[blockIdx.x * 256 + tid] = h0[blockIdx.x * 256 + tid];

    unsigned sense = 0;
    gbar(&sense);

    const int wrp = tid >> 5, lane = tid & 31;
    const int n = blockIdx.x * 8 + wrp;
    const float4* wrow = (const float4*)(WL + (size_t)n * H_);

    for (int c = 1; c < C_; c++) {
        const float4* src = (const float4*)(Hst + (size_t)(c - 1) * (B_ * H_));
        for (int i = tid; i < (B_ * H_) / 4; i += 256) {
            int b = i >> 7, k4 = i & 127;
            *(float4*)&h_s[b * HS_STRIDE + k4 * 4] = src[i];
        }
        __syncthreads();

        const float4* hb = (const float4*)(h_s + lane * HS_STRIDE);
        float acc = 0.f;
        #pragma unroll 4
        for (int q = 0; q < 128; q++) {
            float4 hv = hb[q];
            float4 wv = wrow[q];
            acc = fmaf(hv.x, wv.x, acc); acc = fmaf(hv.y, wv.y, acc);
            acc = fmaf(hv.z, wv.z, acc); acc = fmaf(hv.w, wv.w, acc);
        }
        Hst[(size_t)c * (B_ * H_) + lane * H_ + n] =
            acc + sA[((size_t)(c - 1) * B_ + lane) * H_ + n];
        gbar(&sense);
    }
}

// ---------------- softmax over last dim (O=256), in place ----------------
__global__ __launch_bounds__(128) void softmax_kernel(float* __restrict__ p)
{
    const size_t row = blockIdx.x;
    float* r = p + row * O_;
    const int tid = threadIdx.x;

    float v0 = r[tid], v1 = r[tid + 128];
    float m = fmaxf(v0, v1);
    #pragma unroll
    for (int o = 16; o; o >>= 1) m = fmaxf(m, __shfl_xor_sync(~0u, m, o));
    __shared__ float red[4];
    if ((tid & 31) == 0) red[tid >> 5] = m;
    __syncthreads();
    m = fmaxf(fmaxf(red[0], red[1]), fmaxf(red[2], red[3]));

    float e0 = expf(v0 - m), e1 = expf(v1 - m);
    float s = e0 + e1;
    #pragma unroll
    for (int o = 16; o; o >>= 1) s += __shfl_xor_sync(~0u, s, o);
    __shared__ float red2[4];
    if ((tid & 31) == 0) red2[tid >> 5] = s;
    __syncthreads();
    s = red2[0] + red2[1] + red2[2] + red2[3];

    float inv = 1.f / s;
    r[tid] = e0 * inv;
    r[tid + 128] = e1 * inv;
}

// ---------------- launch ----------------
extern "C" void kernel_launch(void* const* d_in, const int* in_sizes, int n_in,
                              void* d_out, int out_size)
{
    const float* x     = (const float*)d_in[0];
    const float* h0    = (const float*)d_in[1];
    const float* W_ih  = (const float*)d_in[2];
    const float* W_hh  = (const float*)d_in[3];
    const float* b_ih  = (const float*)d_in[4];
    const float* b_hh  = (const float*)d_in[5];
    const float* W_lin = (const float*)d_in[6];
    const float* b_lin = (const float*)d_in[7];
    float* out = (float*)d_out;

    const size_t BTO = (size_t)B_ * T_ * O_;
    const size_t BTH = (size_t)B_ * T_ * H_;

    float* z_ptr = nullptr;
    bool do_out = true;
    if ((size_t)out_size >= BTO + BTH) {
        z_ptr = out + BTO;                          // tuple (out, z) flattened
    } else if ((size_t)out_size == BTH) {
        z_ptr = out; do_out = false;
    } else {
        cudaGetSymbolAddress((void**)&z_ptr, g_z);
    }

    float *xw_p, *SA, *SB, *Hst, *P0, *P1;
    cudaGetSymbolAddress((void**)&xw_p, g_xw);
    cudaGetSymbolAddress((void**)&SA,  g_SA);
    cudaGetSymbolAddress((void**)&SB,  g_SB);
    cudaGetSymbolAddress((void**)&Hst, g_Hst);
    cudaGetSymbolAddress((void**)&P0,  g_P0);
    cudaGetSymbolAddress((void**)&P1,  g_P1);

    cudaFuncSetAttribute(scan_persist,
                         cudaFuncAttributeMaxDynamicSharedMemorySize, SCAN_SMEM);
    cudaFuncSetAttribute(phaseB_kernel,
                         cudaFuncAttributeMaxDynamicSharedMemorySize,
                         B_ * HS_STRIDE * 4);

    // K1: xw = x @ W_ih^T + (b_ih + b_hh)
    {
        dim3 g((B_ * T_) / 128, H_ / 128);
        gemm128_nt<<<g, 256>>>(x, W_ih, b_ih, b_hh, xw_p, B_ * T_, H_, D_);
    }

    // WL = Whh^32 via 5 squarings -> P0
    {
        dim3 g(H_ / 64, H_ / 64);
        matsq_nn<<<g, 256>>>(W_hh, P0);
        matsq_nn<<<g, 256>>>(P0, P1);
        matsq_nn<<<g, 256>>>(P1, P0);
        matsq_nn<<<g, 256>>>(P0, P1);
        matsq_nn<<<g, 256>>>(P1, P0);
    }

    // Phase A: zero-init chunk scan (31 steps, persistent). Final state -> SA.
    scan_persist<<<128, 256, SCAN_SMEM>>>(nullptr, SA, SB, W_hh, xw_p,
                                          nullptr, 1, L_ - 1, 1);

    // Phase B: boundary states
    phaseB_kernel<<<C_, 256, B_ * HS_STRIDE * 4>>>(h0, P0, SA, Hst);

    // Phase C: correct-init chunk scan (32 steps, persistent), writes z.
    scan_persist<<<128, 256, SCAN_SMEM>>>(Hst, SA, SB, W_hh, xw_p,
                                          z_ptr, 0, L_, 0);

    // K3: logits = z @ W_lin^T + b_lin ; softmax over O
    if (do_out) {
        dim3 g((B_ * T_) / 128, O_ / 128);
        gemm128_nt<<<g, 256>>>(z_ptr, W_lin, b_lin, nullptr, out, B_ * T_, O_, H_);
        softmax_kernel<<<B_ * T_, 128>>>(out);
    }
}